// round 17
// baseline (speedup 1.0000x reference)
#include <cuda_runtime.h>
#include <cstdint>

// LSTMModelClassify: B=2048, T=512, D=1, H=50, C=2, 2-layer LSTM + FC.
// R17 = R16 + side1's Wih1 sweep moved into side0's fused loop (G=4):
// side0: Whh0[s](reg) + Whh0[s+100] + Wih1[s] + Wih1[s+100] share ONE h1 stream.
// side1: only Whh1 G=2 @ h2. Removes 364 redundant h1 LDS+wf /block/step.
// Register economy: cell state c1/c2 in smem, biases re-read per step,
// EW indices recomputed — keeps G=4 (56 acc) + wreg (52) under the 128 cap.

#define TPB 256
constexpr int NB    = 7;
constexpr int Hh    = 50;
constexpr int G4    = 200;
constexpr int Tt    = 512;
constexpr int BATCH = 2048;
constexpr int NC    = 2;
constexpr int HS    = 52;    // weight/h row stride (50 + 2 zero pad)
constexpr int GS    = 200;   // plane batch stride (coalesced access -> stride free)
constexpr int NCELL = 350;   // Hh * NB

// shared memory layout (floats)
constexpr int OFF_WI1 = 0;                     // Wih1 [200][52]
constexpr int OFF_WH0 = OFF_WI1 + G4 * HS;     // Whh0 rows 100-199 [100][52]
constexpr int OFF_WH1 = OFF_WH0 + 100 * HS;    // Whh1 rows 100-199 [100][52]
constexpr int OFF_A   = OFF_WH1 + 100 * HS;    // h1 [7][52]
constexpr int OFF_B   = OFF_A   + NB * HS;     // h2 [7][52]
constexpr int OFF_P0  = OFF_B   + NB * HS;     // L1(t+1) preact [b][g]
constexpr int OFF_P1  = OFF_P0  + NB * GS;     // Whh1@h2(t-1) + bias1 [b][g]
constexpr int OFF_P2  = OFF_P1  + NB * GS;     // Wih1@h1(t) [b][g]
constexpr int OFF_BS0 = OFF_P2  + NB * GS;     // bias0 (bih0+bhh0) [200]
constexpr int OFF_BS1 = OFF_BS0 + G4;          // bias1 (bih1+bhh1) [200]
constexpr int OFF_WX  = OFF_BS1 + G4;          // Wih0 column [200]
constexpr int OFF_C1  = OFF_WX  + G4;          // cell state layer1 [350]
constexpr int OFF_C2  = OFF_C1  + NCELL;       // cell state layer2 [350]
constexpr int OFF_WFC = OFF_C2  + NCELL;
constexpr int OFF_BFC = OFF_WFC + NC * Hh;
constexpr int SMEMF   = OFF_BFC + NC;          // ~26.9K floats ≈ 107.7KB

__device__ __forceinline__ unsigned long long ffma2(unsigned long long a,
                                                    unsigned long long b,
                                                    unsigned long long c) {
    unsigned long long d;
    asm("fma.rn.f32x2 %0, %1, %2, %3;" : "=l"(d) : "l"(a), "l"(b), "l"(c));
    return d;
}

__device__ __forceinline__ float hadd2(unsigned long long a) {
    unsigned lo, hi;
    asm("mov.b64 {%0, %1}, %2;" : "=r"(lo), "=r"(hi) : "l"(a));
    return __uint_as_float(lo) + __uint_as_float(hi);
}

__device__ __forceinline__ float sigf(float x) {
    float e = __expf(-x);
    return __fdividef(1.0f, 1.0f + e);
}
__device__ __forceinline__ float tanh_(float x) {
    float e = __expf(2.0f * x);
    return 1.0f - __fdividef(2.0f, 1.0f + e);
}

__global__ void __launch_bounds__(TPB, 2) lstm_kernel(
    const float* __restrict__ x,
    const float* __restrict__ Wih0, const float* __restrict__ Whh0,
    const float* __restrict__ bih0, const float* __restrict__ bhh0,
    const float* __restrict__ Wih1, const float* __restrict__ Whh1,
    const float* __restrict__ bih1, const float* __restrict__ bhh1,
    const float* __restrict__ Wfc,  const float* __restrict__ bfc,
    float* __restrict__ out)
{
    extern __shared__ __align__(16) float sm[];
    const int tid = threadIdx.x;
    const int b0  = blockIdx.x * NB;

    for (int i = tid; i < SMEMF; i += TPB) sm[i] = 0.0f;   // zero: pads+h2+cells
    __syncthreads();

    float* WI1  = sm + OFF_WI1;
    float* WH0  = sm + OFF_WH0;
    float* WH1  = sm + OFF_WH1;
    float* bufA = sm + OFF_A;
    float* bufB = sm + OFF_B;
    float* P0   = sm + OFF_P0;
    float* P1   = sm + OFF_P1;
    float* P2   = sm + OFF_P2;
    float* BS0  = sm + OFF_BS0;
    float* BS1  = sm + OFF_BS1;
    float* WX   = sm + OFF_WX;
    float* C1   = sm + OFF_C1;
    float* C2   = sm + OFF_C2;
    float* wfc  = sm + OFF_WFC;
    float* bfcs = sm + OFF_BFC;

    // stage Wih1 (full), Whh0/Whh1 rows 100-199, biases/wx, fc
    for (int i = tid; i < G4 * Hh; i += TPB) {
        int g = i / Hh, k = i % Hh;
        WI1[g * HS + k] = Wih1[i];
    }
    for (int i = tid; i < 100 * Hh; i += TPB) {
        int g = i / Hh, k = i % Hh;
        WH0[g * HS + k] = Whh0[(g + 100) * Hh + k];
        WH1[g * HS + k] = Whh1[(g + 100) * Hh + k];
    }
    for (int i = tid; i < G4; i += TPB) {
        BS0[i] = bih0[i] + bhh0[i];
        BS1[i] = bih1[i] + bhh1[i];
        WX[i]  = Wih0[i];
    }
    for (int i = tid; i < NC * Hh; i += TPB) wfc[i] = Wfc[i];
    if (tid < NC) bfcs[tid] = bfc[tid];

    // ---- warp-aligned roles ----
    const int  warp  = tid >> 5;
    const int  lane  = tid & 31;
    const bool side1 = warp >= 4;
    const int  wq    = warp & 3;
    const bool gact  = lane < 25;
    const int  s     = wq * 25 + (gact ? lane : 24);   // 0..99 (clamped)

    // register weights: row s of Whh0 (side0) or Whh1 (side1)
    unsigned long long wreg[26];
    {
        const float* wsrc = side1 ? (Whh1 + s * Hh) : (Whh0 + s * Hh);
        const unsigned long long* ws = reinterpret_cast<const unsigned long long*>(wsrc);
#pragma unroll
        for (int i = 0; i < 25; ++i) wreg[i] = ws[i];
        wreg[25] = 0ULL;
    }
    const float* wsRow = (side1 ? WH1 : WH0) + s * HS;   // streamed recurrent row s+100
    const float* wiRow = WI1 + s * HS;                   // side0: Wih1 rows s, s+100(+5200)

    const int   bmax  = BATCH - b0;                      // valid batches in this block
    const float* xbase = x + (long long)b0 * Tt;

    __syncthreads();

    // ---- prologue: h1(0) from Wih0*x(0)+bias0; C1 init (C2 zeroed above) ----
#pragma unroll
    for (int r = 0; r < 2; ++r) {
        int u = tid + TPB * r;
        if (u < NCELL) {
            int b = u / Hh, j = u % Hh;
            float xv = (b < bmax) ? __ldg(xbase + b * Tt) : 0.0f;
            float pi = fmaf(WX[j],       xv, BS0[j]);
            float pf = fmaf(WX[j + 50],  xv, BS0[j + 50]);
            float pg = fmaf(WX[j + 100], xv, BS0[j + 100]);
            float po = fmaf(WX[j + 150], xv, BS0[j + 150]);
            float cc = sigf(pi) * tanh_(pg);
            C1[u] = cc;
            bufA[b * HS + j] = sigf(po) * tanh_(cc);
        }
    }
    __syncthreads();

    for (int t = 0; t < Tt; ++t) {
        const int txn = (t + 1 < Tt) ? (t + 1) : (Tt - 1);

        if (!side1) {
            // ---- side0 FUSED G=4: one h1(t) stream feeds Whh0[s](reg),
            //      Whh0[s+100], Wih1[s], Wih1[s+100] (smem) ----
            unsigned long long a0[NB], a1[NB], a2[NB], a3[NB];
#pragma unroll
            for (int b = 0; b < NB; ++b) { a0[b]=0ULL; a1[b]=0ULL; a2[b]=0ULL; a3[b]=0ULL; }
#pragma unroll
            for (int k4 = 0; k4 < 13; ++k4) {
                ulonglong2 wv1 = *reinterpret_cast<const ulonglong2*>(wsRow + 4 * k4);
                ulonglong2 wv2 = *reinterpret_cast<const ulonglong2*>(wiRow + 4 * k4);
                ulonglong2 wv3 = *reinterpret_cast<const ulonglong2*>(wiRow + 5200 + 4 * k4);
#pragma unroll
                for (int b = 0; b < NB; ++b) {
                    ulonglong2 hv = *reinterpret_cast<const ulonglong2*>(bufA + b * HS + 4 * k4);
                    a0[b] = ffma2(hv.x, wreg[2 * k4],     a0[b]);
                    a0[b] = ffma2(hv.y, wreg[2 * k4 + 1], a0[b]);
                    a1[b] = ffma2(hv.x, wv1.x, a1[b]);
                    a1[b] = ffma2(hv.y, wv1.y, a1[b]);
                    a2[b] = ffma2(hv.x, wv2.x, a2[b]);
                    a2[b] = ffma2(hv.y, wv2.y, a2[b]);
                    a3[b] = ffma2(hv.x, wv3.x, a3[b]);
                    a3[b] = ffma2(hv.y, wv3.y, a3[b]);
                }
            }
            if (gact) {
                float bA0 = BS0[s], bA1 = BS0[s + 100];
                float wx0 = WX[s],  wx1 = WX[s + 100];
#pragma unroll
                for (int b = 0; b < NB; ++b) {
                    float xv = (b < bmax) ? __ldg(xbase + b * Tt + txn) : 0.0f;
                    P0[b * GS + s]       = hadd2(a0[b]) + fmaf(wx0, xv, bA0);
                    P0[b * GS + s + 100] = hadd2(a1[b]) + fmaf(wx1, xv, bA1);
                    P2[b * GS + s]       = hadd2(a2[b]);
                    P2[b * GS + s + 100] = hadd2(a3[b]);
                }
            }
        } else {
            // ---- side1 G=2: Whh1 rows (s reg, s+100 smem) @ h2(t-1) ----
            unsigned long long a0[NB], a1[NB];
#pragma unroll
            for (int b = 0; b < NB; ++b) { a0[b] = 0ULL; a1[b] = 0ULL; }
#pragma unroll
            for (int k4 = 0; k4 < 13; ++k4) {
                ulonglong2 wv = *reinterpret_cast<const ulonglong2*>(wsRow + 4 * k4);
#pragma unroll
                for (int b = 0; b < NB; ++b) {
                    ulonglong2 hv = *reinterpret_cast<const ulonglong2*>(bufB + b * HS + 4 * k4);
                    a0[b] = ffma2(hv.x, wreg[2 * k4],     a0[b]);
                    a0[b] = ffma2(hv.y, wreg[2 * k4 + 1], a0[b]);
                    a1[b] = ffma2(hv.x, wv.x, a1[b]);
                    a1[b] = ffma2(hv.y, wv.y, a1[b]);
                }
            }
            if (gact) {
                float bA0 = BS1[s], bA1 = BS1[s + 100];
#pragma unroll
                for (int b = 0; b < NB; ++b) {
                    P1[b * GS + s]       = hadd2(a0[b]) + bA0;
                    P1[b * GS + s + 100] = hadd2(a1[b]) + bA1;
                }
            }
        }
        __syncthreads();

        // ---- EW: h2(t) from P1+P2; h1(t+1) from P0 (cell state in smem) ----
#pragma unroll
        for (int r = 0; r < 2; ++r) {
            int u = tid + TPB * r;
            if (u < NCELL) {
                int b = u / Hh, j = u % Hh;
                const float* p1b = P1 + b * GS + j;
                const float* p2b = P2 + b * GS + j;
                const float* p0b = P0 + b * GS + j;
                // layer 2 at t
                {
                    float pi = p1b[0]   + p2b[0];
                    float pf = p1b[50]  + p2b[50];
                    float pg = p1b[100] + p2b[100];
                    float po = p1b[150] + p2b[150];
                    float cc = sigf(pf) * C2[u] + sigf(pi) * tanh_(pg);
                    C2[u] = cc;
                    bufB[b * HS + j] = sigf(po) * tanh_(cc);
                }
                // layer 1 at t+1
                {
                    float pi = p0b[0];
                    float pf = p0b[50];
                    float pg = p0b[100];
                    float po = p0b[150];
                    float cc = sigf(pf) * C1[u] + sigf(pi) * tanh_(pg);
                    C1[u] = cc;
                    bufA[b * HS + j] = sigf(po) * tanh_(cc);
                }
            }
        }
        __syncthreads();
    }

    // ---- Final FC on h2(511) ----
    if (tid < NB * NC) {
        int bl = tid >> 1;
        int c  = tid & 1;
        int gb = b0 + bl;
        if (gb < BATCH) {
            float sacc = bfcs[c];
#pragma unroll
            for (int j = 0; j < Hh; ++j) sacc += wfc[c * Hh + j] * bufB[bl * HS + j];
            out[gb * NC + c] = sacc;
        }
    }
}

extern "C" void kernel_launch(void* const* d_in, const int* in_sizes, int n_in,
                              void* d_out, int out_size) {
    const float* x    = (const float*)d_in[0];
    const float* Wih0 = (const float*)d_in[1];
    const float* Whh0 = (const float*)d_in[2];
    const float* bih0 = (const float*)d_in[3];
    const float* bhh0 = (const float*)d_in[4];
    const float* Wih1 = (const float*)d_in[5];
    const float* Whh1 = (const float*)d_in[6];
    const float* bih1 = (const float*)d_in[7];
    const float* bhh1 = (const float*)d_in[8];
    const float* Wfc  = (const float*)d_in[9];
    const float* bfc  = (const float*)d_in[10];
    float* out = (float*)d_out;

    const int smem_bytes = SMEMF * (int)sizeof(float);
    cudaFuncSetAttribute(lstm_kernel, cudaFuncAttributeMaxDynamicSharedMemorySize, smem_bytes);

    const int grid = (BATCH + NB - 1) / NB;   // 293 blocks, 2 per SM
    lstm_kernel<<<grid, TPB, smem_bytes>>>(x, Wih0, Whh0, bih0, bhh0,
                                           Wih1, Whh1, bih1, bhh1,
                                           Wfc, bfc, out);
}